// round 1
// baseline (speedup 1.0000x reference)
#include <cuda_runtime.h>
#include <cstdint>

#define B_ 2
#define S_ 1024
#define D_ 128

typedef unsigned long long u64;

// ---------------- scratch (static __device__, no allocs) ----------------
__device__ float g_Qt[B_*D_*S_];     // Q transposed [b][d][s]
__device__ float g_Kt[B_*D_*S_];     // K transposed [b][d][s]
__device__ float g_sumK[B_*S_];      // sum_d K[b][s][d]
__device__ float g_V[B_*S_*D_];      // V [b][s][d]
__device__ float g_Et[B_*S_*S_];     // exp(10T) transposed [b][k][q] (0 where k>q)
__device__ float g_Z[B_*S_];         // row sums of E (lower triangle only)

__device__ __forceinline__ u64 pack2(float a, float b){
  u64 r; asm("mov.b64 %0, {%1, %2};" : "=l"(r) : "f"(a), "f"(b)); return r;
}
__device__ __forceinline__ void unpack2(u64 v, float& a, float& b){
  asm("mov.b64 {%0, %1}, %2;" : "=f"(a), "=f"(b) : "l"(v));
}
__device__ __forceinline__ u64 fma2(u64 a, u64 b, u64 c){
  u64 d; asm("fma.rn.f32x2 %0, %1, %2, %3;" : "=l"(d) : "l"(a), "l"(b), "l"(c)); return d;
}

// ---------------- K0: zero attention region of d_out + g_Z ----------------
__global__ void k_zero(float* __restrict__ att){
  int i = blockIdx.x*blockDim.x + threadIdx.x;   // exactly B*S*S/4 threads
  ((float4*)att)[i] = make_float4(0.f,0.f,0.f,0.f);
  if (i < B_*S_) g_Z[i] = 0.f;
}

// ---------------- K1: QKV projection + sigmoid + transposed stores --------
__global__ void __launch_bounds__(128) k_qkv(
    const float* __restrict__ x,
    const float* __restrict__ wq, const float* __restrict__ bq,
    const float* __restrict__ wk, const float* __restrict__ bk,
    const float* __restrict__ wv, const float* __restrict__ bv){
  __shared__ float xs[128][16];   // [d][s] transposed tile
  __shared__ float wred[4][16];
  int t = threadIdx.x;            // output dim
  int s0 = blockIdx.x*16;         // global row base (batches don't straddle)
  int b = s0 >> 10;
  #pragma unroll
  for (int s=0;s<16;s++) xs[t][s] = x[(s0+s)*D_ + t];
  __syncthreads();

  u64 aq[8], ak[8], av[8];
  #pragma unroll
  for (int p=0;p<8;p++){ aq[p]=0ull; ak[p]=0ull; av[p]=0ull; }

  #pragma unroll 4
  for (int d=0; d<128; d++){
    float w1 = wq[d*D_+t], w2 = wk[d*D_+t], w3 = wv[d*D_+t];
    u64 w1p = pack2(w1,w1), w2p = pack2(w2,w2), w3p = pack2(w3,w3);
    const u64* xr = (const u64*)&xs[d][0];
    #pragma unroll
    for (int p=0;p<8;p++){
      u64 xp = xr[p];
      aq[p] = fma2(xp, w1p, aq[p]);
      ak[p] = fma2(xp, w2p, ak[p]);
      av[p] = fma2(xp, w3p, av[p]);
    }
  }

  float bqv = bq[t], bkv = bk[t], bvv = bv[t];
  float qv[16], kv[16], vv[16];
  #pragma unroll
  for (int p=0;p<8;p++){
    float a0,a1;
    unpack2(aq[p],a0,a1); qv[2*p]=a0+bqv; qv[2*p+1]=a1+bqv;
    unpack2(ak[p],a0,a1); kv[2*p]=a0+bkv; kv[2*p+1]=a1+bkv;
    unpack2(av[p],a0,a1); vv[2*p]=a0+bvv; vv[2*p+1]=a1+bvv;
  }
  #pragma unroll
  for (int s=0;s<16;s++){
    qv[s] = 1.f/(1.f+__expf(-qv[s]));
    kv[s] = 1.f/(1.f+__expf(-kv[s]));
  }

  int sl = s0 - (b<<10);
  float* qtp = g_Qt + b*D_*S_ + t*S_ + sl;
  float* ktp = g_Kt + b*D_*S_ + t*S_ + sl;
  #pragma unroll
  for (int s=0;s<16;s++){
    qtp[s] = qv[s];
    ktp[s] = kv[s];
    g_V[(s0+s)*D_ + t] = vv[s];
  }

  // sumK over t (128 lanes, 4 warps)
  float red[16];
  #pragma unroll
  for (int s=0;s<16;s++) red[s]=kv[s];
  #pragma unroll
  for (int off=16; off>=1; off>>=1){
    #pragma unroll
    for (int s=0;s<16;s++) red[s] += __shfl_xor_sync(0xffffffffu, red[s], off);
  }
  if ((t&31)==0){
    int w = t>>5;
    #pragma unroll
    for (int s=0;s<16;s++) wred[w][s] = red[s];
  }
  __syncthreads();
  if (t < 16) g_sumK[s0 + t] = wred[0][t]+wred[1][t]+wred[2][t]+wred[3][t];
}

// ---------------- K1b: suffix sums of V -> output region of d_out --------
__global__ void __launch_bounds__(1024) k_suffv(float* __restrict__ outp){
  int b = blockIdx.x;
  int t = threadIdx.x;
  int d = t & 127, c = t >> 7;       // 8 chunks of 128 k's
  __shared__ float csum[8][128];
  const float* Vb = g_V + b*S_*D_;
  float acc = 0.f;
  int k0 = c*128;
  for (int k=k0; k<k0+128; k++) acc += Vb[k*D_ + d];
  csum[c][d] = acc;
  __syncthreads();
  float a = 0.f;
  for (int cc=c+1; cc<8; cc++) a += csum[cc][d];
  float* ob = outp + b*S_*D_;
  for (int kk=k0+127; kk>=k0; kk--){
    ob[kk*D_ + d] = a;              // suffV[kk] = sum_{j>kk} V[j]
    a += Vb[kk*D_ + d];
  }
}

// ---------------- K2: attention_truth (lower triangle) + E + Z -----------
// 144 blocks: b in {0,1}, qt 0..7 (128 q's), kt 0..2(qt+1)-1 (64 k's each)
__global__ void __launch_bounds__(256) k_truth(float* __restrict__ outp){
  extern __shared__ float sm[];
  float* Qts = sm;               // [128 d][128 q]
  float* Kts = sm + 128*128;     // [128 d][64 k]
  float* sKs = Kts + 128*64;     // [64]
  int bid = blockIdx.x;
  int b = bid/72, r = bid - b*72;
  int qt = 0;
  while ((qt+1)*(qt+2) <= r) qt++;
  int k0 = (r - qt*(qt+1))*64;
  int q0 = qt*128;
  int t = threadIdx.x, tx = t & 15, ty = t >> 4;

  float4* Qts4 = (float4*)Qts;
  float4* Kts4 = (float4*)Kts;
  const float4* Qg = (const float4*)(g_Qt + b*D_*S_);
  const float4* Kg = (const float4*)(g_Kt + b*D_*S_);
  #pragma unroll
  for (int it=0; it<16; it++){
    int i = t + it*256;                     // 4096 float4
    int row = i>>5, col = i&31;
    Qts4[i] = Qg[row*256 + (q0>>2) + col];
  }
  #pragma unroll
  for (int it=0; it<8; it++){
    int i = t + it*256;                     // 2048 float4
    int row = i>>4, col = i&15;
    Kts4[i] = Kg[row*256 + (k0>>2) + col];
  }
  if (t < 64) sKs[t] = g_sumK[b*S_ + k0 + t];
  __syncthreads();

  float acc[8][4];
  #pragma unroll
  for (int i=0;i<8;i++)
    #pragma unroll
    for (int j=0;j<4;j++) acc[i][j] = 0.f;

  #pragma unroll 4
  for (int d=0; d<128; d++){
    float4 qa = Qts4[d*32 + ty*2];
    float4 qb = Qts4[d*32 + ty*2 + 1];
    float4 kf = Kts4[d*16 + tx];
    float qv[8] = {qa.x,qa.y,qa.z,qa.w,qb.x,qb.y,qb.z,qb.w};
    float kk[4] = {kf.x,kf.y,kf.z,kf.w};
    float km[4] = {1.f-kf.x, 1.f-kf.y, 1.f-kf.z, 1.f-kf.w};
    #pragma unroll
    for (int i=0;i<8;i++){
      #pragma unroll
      for (int j=0;j<4;j++){
        // acc += (q <= k) ? (1-k) : 0   -- forced FSETP + predicated FADD
        asm("{.reg .pred p; setp.le.f32 p, %1, %2; @p add.f32 %0, %0, %3;}"
            : "+f"(acc[i][j]) : "f"(qv[i]), "f"(kk[j]), "f"(km[j]));
      }
    }
  }

  float* att = outp + B_*S_*D_;
  const float inv = 1.f/128.f;
  float e[8][4];
  #pragma unroll
  for (int i=0;i<8;i++){
    int qg = q0 + ty*8 + i;
    float zrow = 0.f;
    float tt[4];
    #pragma unroll
    for (int j=0;j<4;j++){
      int kg = k0 + tx*4 + j;
      float T = (acc[i][j] + sKs[tx*4+j]) * inv;
      bool val = (kg <= qg);
      T = val ? T : 0.f;
      float ee = val ? __expf(10.f*T) : 0.f;
      tt[j] = T; e[i][j] = ee; zrow += ee;
    }
    ((float4*)(att + (b*S_ + qg)*S_ + k0 + tx*4))[0] =
        make_float4(tt[0],tt[1],tt[2],tt[3]);
    #pragma unroll
    for (int off=8; off>=1; off>>=1)
      zrow += __shfl_xor_sync(0xffffffffu, zrow, off);
    if (tx == 0) atomicAdd(&g_Z[b*S_ + qg], zrow);
  }
  // store E transposed [k][q] for the AV GEMM
  #pragma unroll
  for (int j=0;j<4;j++){
    int kg = k0 + tx*4 + j;
    float* ep = g_Et + (b*S_ + kg)*S_ + q0 + ty*8;
    ((float4*)ep)[0] = make_float4(e[0][j],e[1][j],e[2][j],e[3][j]);
    ((float4*)ep)[1] = make_float4(e[4][j],e[5][j],e[6][j],e[7][j]);
  }
}

// ---------------- K3: out += E @ V (split-K atomics, f32x2 FFMA) ---------
__global__ void __launch_bounds__(256) k_av(float* __restrict__ outp){
  extern __shared__ float sm[];
  float* Es = sm;                 // [64 k][128 q]
  float* Vs = sm + 64*128;        // [64 k][128 d]
  int bid = blockIdx.x;
  int b = bid/72, r = bid - b*72;
  int qt = 0;
  while ((qt+1)*(qt+2) <= r) qt++;
  int k0 = (r - qt*(qt+1))*64;
  int q0 = qt*128;
  int t = threadIdx.x, tx = t & 15, ty = t >> 4;

  float4* Es4 = (float4*)Es;
  float4* Vs4 = (float4*)Vs;
  const float4* Eg = (const float4*)(g_Et + b*S_*S_);
  const float4* Vg = (const float4*)(g_V + b*S_*D_);
  #pragma unroll
  for (int it=0; it<8; it++){
    int i = t + it*256;                     // 2048 float4 each
    int row = i>>5, col = i&31;
    Es4[i] = Eg[(k0+row)*256 + (q0>>2) + col];
    Vs4[i] = Vg[(k0+row)*32 + col];
  }
  __syncthreads();

  u64 acc2[8][4];
  #pragma unroll
  for (int i=0;i<8;i++)
    #pragma unroll
    for (int j=0;j<4;j++) acc2[i][j] = 0ull;

  #pragma unroll 2
  for (int k=0;k<64;k++){
    float4 ea = Es4[k*32 + ty*2];
    float4 eb = Es4[k*32 + ty*2 + 1];
    const u64* vr = (const u64*)&Vs[k*128 + tx*8];
    u64 v0 = vr[0], v1 = vr[1], v2 = vr[2], v3 = vr[3];
    float ev[8] = {ea.x,ea.y,ea.z,ea.w,eb.x,eb.y,eb.z,eb.w};
    #pragma unroll
    for (int i=0;i<8;i++){
      u64 e2 = pack2(ev[i], ev[i]);
      acc2[i][0] = fma2(e2, v0, acc2[i][0]);
      acc2[i][1] = fma2(e2, v1, acc2[i][1]);
      acc2[i][2] = fma2(e2, v2, acc2[i][2]);
      acc2[i][3] = fma2(e2, v3, acc2[i][3]);
    }
  }

  #pragma unroll
  for (int i=0;i<8;i++){
    int qg = q0 + ty*8 + i;
    float* op = outp + (b*S_ + qg)*D_ + tx*8;
    #pragma unroll
    for (int j=0;j<4;j++){
      float a0,a1; unpack2(acc2[i][j],a0,a1);
      atomicAdd(op + 2*j,     a0);
      atomicAdd(op + 2*j + 1, a1);
    }
  }
}

// ---------------- K4: normalize by softmax denominator -------------------
__global__ void k_norm(float* __restrict__ outp){
  int q = blockIdx.x;            // global row 0..2047
  int t = threadIdx.x;           // d
  int ql = q & 1023;
  float z = g_Z[q] + (float)(1023 - ql);
  outp[q*D_ + t] *= (1.f/z);
}

// ---------------- launch ----------------
extern "C" void kernel_launch(void* const* d_in, const int* in_sizes, int n_in,
                              void* d_out, int out_size){
  (void)in_sizes; (void)n_in; (void)out_size;
  const float* x  = (const float*)d_in[0];
  const float* wq = (const float*)d_in[1];
  const float* bq = (const float*)d_in[2];
  const float* wk = (const float*)d_in[3];
  const float* bk = (const float*)d_in[4];
  const float* wv = (const float*)d_in[5];
  const float* bv = (const float*)d_in[6];
  float* out = (float*)d_out;
  float* att = out + B_*S_*D_;   // assume tuple order: (output, attention_truth)

  const int SM2 = (128*128 + 128*64 + 64) * 4;   // 96.25 KB
  const int SM3 = 64*128*2 * 4;                   // 64 KB
  cudaFuncSetAttribute(k_truth, cudaFuncAttributeMaxDynamicSharedMemorySize, SM2);
  cudaFuncSetAttribute(k_av,    cudaFuncAttributeMaxDynamicSharedMemorySize, SM3);

  k_zero <<< (B_*S_*S_/4)/256, 256 >>>(att);
  k_qkv  <<< (B_*S_)/16, 128 >>>(x, wq, bq, wk, bk, wv, bv);
  k_suffv<<< B_, 1024 >>>(out);
  k_truth<<< 144, 256, SM2 >>>(out);
  k_av   <<< 144, 256, SM3 >>>(out);
  k_norm <<< B_*S_, 128 >>>(out);
}

// round 2
// speedup vs baseline: 1.6416x; 1.6416x over previous
#include <cuda_runtime.h>
#include <cstdint>

#define B_ 2
#define S_ 1024
#define D_ 128

typedef unsigned long long u64;

// ---------------- scratch ----------------
__device__ float g_Qt[B_*D_*S_];     // Q transposed [b][d][s]
__device__ float g_Kt[B_*D_*S_];     // K transposed [b][d][s]
__device__ float g_sumK[B_*S_];      // sum_d K[b][s][d]
__device__ float g_V[B_*S_*D_];      // V [b][s][d]
__device__ float g_Z[B_*S_];         // row sums of E' (lower triangle)
__device__ float g_totV[B_*D_];      // sum_s V[b][s][d]

__device__ __forceinline__ u64 pack2(float a, float b){
  u64 r; asm("mov.b64 %0, {%1, %2};" : "=l"(r) : "f"(a), "f"(b)); return r;
}
__device__ __forceinline__ void unpack2(u64 v, float& a, float& b){
  asm("mov.b64 {%0, %1}, %2;" : "=f"(a), "=f"(b) : "l"(v));
}
__device__ __forceinline__ u64 fma2(u64 a, u64 b, u64 c){
  u64 d; asm("fma.rn.f32x2 %0, %1, %2, %3;" : "=l"(d) : "l"(a), "l"(b), "l"(c)); return d;
}

// ---------------- K0: zero d_out + g_Z + g_totV ----------------
__global__ void __launch_bounds__(256) k_zero(float* __restrict__ dout){
  int i = blockIdx.x*256 + threadIdx.x;            // 589824 float4 = full d_out
  ((float4*)dout)[i] = make_float4(0.f,0.f,0.f,0.f);
  if (i < B_*S_) g_Z[i] = 0.f;
  if (i < B_*D_) g_totV[i] = 0.f;
}

// ---------------- K1: QKV + sigmoid + transposed Q/K + sumK + totV -------
__global__ void __launch_bounds__(256) k_qkv(
    const float* __restrict__ x,
    const float* __restrict__ wq, const float* __restrict__ bq,
    const float* __restrict__ wk, const float* __restrict__ bk,
    const float* __restrict__ wv, const float* __restrict__ bv){
  __shared__ float xs[128][16];   // [d][s]
  __shared__ float wred[8][8];
  int t = threadIdx.x;
  int o = t & 127;                // output dim
  int h = t >> 7;                 // row half (8 rows each)
  int s0 = blockIdx.x*16;
  int b  = s0 >> 10;
  int sl = s0 & 1023;

  #pragma unroll
  for (int it=0; it<8; it++){
    int i = t + it*256;           // i = s*128 + d
    xs[i & 127][i >> 7] = x[s0*128 + i];
  }
  __syncthreads();

  u64 aq[4], ak[4], av[4];
  #pragma unroll
  for (int p=0;p<4;p++){ aq[p]=0ull; ak[p]=0ull; av[p]=0ull; }

  #pragma unroll 4
  for (int d=0; d<128; d++){
    float w1 = wq[d*D_+o], w2 = wk[d*D_+o], w3 = wv[d*D_+o];
    u64 w1p = pack2(w1,w1), w2p = pack2(w2,w2), w3p = pack2(w3,w3);
    const u64* xr = (const u64*)&xs[d][h*8];
    #pragma unroll
    for (int p=0;p<4;p++){
      u64 xp = xr[p];
      aq[p] = fma2(xp, w1p, aq[p]);
      ak[p] = fma2(xp, w2p, ak[p]);
      av[p] = fma2(xp, w3p, av[p]);
    }
  }

  float bqv = bq[o], bkv = bk[o], bvv = bv[o];
  float qv[8], kv[8], vv[8];
  #pragma unroll
  for (int p=0;p<4;p++){
    float a0,a1;
    unpack2(aq[p],a0,a1); qv[2*p]=a0+bqv; qv[2*p+1]=a1+bqv;
    unpack2(ak[p],a0,a1); kv[2*p]=a0+bkv; kv[2*p+1]=a1+bkv;
    unpack2(av[p],a0,a1); vv[2*p]=a0+bvv; vv[2*p+1]=a1+bvv;
  }
  #pragma unroll
  for (int s=0;s<8;s++){
    qv[s] = 1.f/(1.f+__expf(-qv[s]));
    kv[s] = 1.f/(1.f+__expf(-kv[s]));
  }

  // V stores (coalesced) + totV partial
  float sv = 0.f;
  #pragma unroll
  for (int s=0;s<8;s++){
    g_V[(s0 + h*8 + s)*D_ + o] = vv[s];
    sv += vv[s];
  }
  atomicAdd(&g_totV[b*D_ + o], sv);

  // sumK: warp reduce over o lanes
  float red[8];
  #pragma unroll
  for (int s=0;s<8;s++) red[s] = kv[s];
  #pragma unroll
  for (int off=16; off>=1; off>>=1){
    #pragma unroll
    for (int s=0;s<8;s++) red[s] += __shfl_xor_sync(0xffffffffu, red[s], off);
  }
  int w = t >> 5;
  if ((t & 31) == 0){
    #pragma unroll
    for (int s=0;s<8;s++) wred[w][s] = red[s];
  }
  __syncthreads();
  if (t < 16){
    int hh = t >> 3, ss = t & 7;
    g_sumK[s0 + hh*8 + ss] =
      wred[hh*4+0][ss] + wred[hh*4+1][ss] + wred[hh*4+2][ss] + wred[hh*4+3][ss];
  }

  // stage + coalesced stores for Q then K (xs reuse; all xs reads done)
  __syncthreads();
  #pragma unroll
  for (int s=0;s<8;s++) xs[o][h*8+s] = qv[s];
  __syncthreads();
  {
    int oo = t >> 1, hh = t & 1;
    float4* src = (float4*)&xs[oo][hh*8];
    float4* dst = (float4*)(g_Qt + b*D_*S_ + oo*S_ + sl + hh*8);
    dst[0] = src[0]; dst[1] = src[1];
  }
  __syncthreads();
  #pragma unroll
  for (int s=0;s<8;s++) xs[o][h*8+s] = kv[s];
  __syncthreads();
  {
    int oo = t >> 1, hh = t & 1;
    float4* src = (float4*)&xs[oo][hh*8];
    float4* dst = (float4*)(g_Kt + b*D_*S_ + oo*S_ + sl + hh*8);
    dst[0] = src[0]; dst[1] = src[1];
  }
}

// ---------------- K2: fused truth + E' + Z + E'@V ------------------------
// 144 blocks: b in {0,1}, q-tile 128, k-tile 64 over lower triangle
__global__ void __launch_bounds__(512) k_main(float* __restrict__ outp){
  extern __shared__ float sm[];
  float* Qts = sm;               // [128 d][128 q]  (64KB)  -> reused as Vs
  float* Kts = sm + 128*128;     // [128 d][64 k]   (32KB)  -> reused as Es
  float* sKs = Kts + 128*64;     // [64]
  int bid = blockIdx.x;
  int b = bid/72, r = bid - b*72;
  int qt = 0;
  while ((qt+1)*(qt+2) <= r) qt++;
  int k0 = (r - qt*(qt+1))*64;
  int q0 = qt*128;
  int t = threadIdx.x, tx = t & 15, ty = t >> 4;   // ty 0..31

  float4* Qts4 = (float4*)Qts;
  float4* Kts4 = (float4*)Kts;
  const float4* Qg = (const float4*)(g_Qt + b*D_*S_);
  const float4* Kg = (const float4*)(g_Kt + b*D_*S_);
  #pragma unroll
  for (int it=0; it<8; it++){
    int i = t + it*512;                     // 4096 float4
    Qts4[i] = Qg[(i>>5)*256 + (q0>>2) + (i&31)];
  }
  #pragma unroll
  for (int it=0; it<4; it++){
    int i = t + it*512;                     // 2048 float4
    Kts4[i] = Kg[(i>>4)*256 + (k0>>2) + (i&15)];
  }
  if (t < 64) sKs[t] = g_sumK[b*S_ + k0 + t];
  __syncthreads();

  // phase 1: truth counts (4q x 4k per thread)
  float acc[4][4];
  #pragma unroll
  for (int i=0;i<4;i++)
    #pragma unroll
    for (int j=0;j<4;j++) acc[i][j] = 0.f;

  #pragma unroll 4
  for (int d=0; d<128; d++){
    float4 qa = Qts4[d*32 + ty];
    float4 kf = Kts4[d*16 + tx];
    float qv[4] = {qa.x,qa.y,qa.z,qa.w};
    float kk[4] = {kf.x,kf.y,kf.z,kf.w};
    float km[4] = {1.f-kf.x, 1.f-kf.y, 1.f-kf.z, 1.f-kf.w};
    #pragma unroll
    for (int i=0;i<4;i++){
      #pragma unroll
      for (int j=0;j<4;j++){
        asm("{.reg .pred p; setp.le.f32 p, %1, %2; @p add.f32 %0, %0, %3;}"
            : "+f"(acc[i][j]) : "f"(qv[i]), "f"(kk[j]), "f"(km[j]));
      }
    }
  }

  // phase 2: T, att store, E' = exp(10T)-1, Z' row sums
  float* att = outp + B_*S_*D_;
  const float inv = 1.f/128.f;
  float e[4][4];
  #pragma unroll
  for (int i=0;i<4;i++){
    int qg = q0 + ty*4 + i;
    float zrow = 0.f;
    float tt[4];
    #pragma unroll
    for (int j=0;j<4;j++){
      int kg = k0 + tx*4 + j;
      float T = (acc[i][j] + sKs[tx*4+j]) * inv;
      bool val = (kg <= qg);
      T = val ? T : 0.f;
      float ee = val ? (__expf(10.f*T) - 1.f) : 0.f;
      tt[j] = T; e[i][j] = ee; zrow += ee;
    }
    ((float4*)(att + (b*S_ + qg)*S_ + k0 + tx*4))[0] =
        make_float4(tt[0],tt[1],tt[2],tt[3]);
    #pragma unroll
    for (int off=8; off>=1; off>>=1)
      zrow += __shfl_xor_sync(0xffffffffu, zrow, off);
    if (tx == 0) atomicAdd(&g_Z[b*S_ + qg], zrow);
  }
  __syncthreads();    // everyone done reading Qts/Kts

  // phase 3: stage E' (Kts region) + load V (Qts region)
  float* Es = Kts;               // [64 k][128 q]
  float* Vs = Qts;               // [64 k][128 d]
  #pragma unroll
  for (int j=0;j<4;j++){
    int kl = tx*4 + j;
    ((float4*)(Es + kl*128 + ty*4))[0] =
        make_float4(e[0][j], e[1][j], e[2][j], e[3][j]);
  }
  const float4* Vg = (const float4*)(g_V + b*S_*D_);
  float4* Vs4 = (float4*)Vs;
  #pragma unroll
  for (int it=0; it<4; it++){
    int i = t + it*512;
    Vs4[i] = Vg[(k0 + (i>>5))*32 + (i&31)];
  }
  __syncthreads();

  // phase 4: out[q0:q0+128][:] += E'^T @ V   (4q x 8d per thread, f32x2)
  u64 acc2[4][4];
  #pragma unroll
  for (int i=0;i<4;i++)
    #pragma unroll
    for (int j=0;j<4;j++) acc2[i][j] = 0ull;

  float4* Es4 = (float4*)Es;
  #pragma unroll 2
  for (int k=0;k<64;k++){
    float4 ef = Es4[k*32 + ty];
    const u64* vr = (const u64*)(Vs + k*128 + tx*8);
    u64 v0 = vr[0], v1 = vr[1], v2 = vr[2], v3 = vr[3];
    float ev[4] = {ef.x,ef.y,ef.z,ef.w};
    #pragma unroll
    for (int i=0;i<4;i++){
      u64 e2 = pack2(ev[i], ev[i]);
      acc2[i][0] = fma2(e2, v0, acc2[i][0]);
      acc2[i][1] = fma2(e2, v1, acc2[i][1]);
      acc2[i][2] = fma2(e2, v2, acc2[i][2]);
      acc2[i][3] = fma2(e2, v3, acc2[i][3]);
    }
  }

  #pragma unroll
  for (int i=0;i<4;i++){
    int qg = q0 + ty*4 + i;
    float* op = outp + (b*S_ + qg)*D_ + tx*8;
    float a0,a1,a2,a3,a4,a5,a6,a7;
    unpack2(acc2[i][0],a0,a1);
    unpack2(acc2[i][1],a2,a3);
    unpack2(acc2[i][2],a4,a5);
    unpack2(acc2[i][3],a6,a7);
    atomicAdd((float4*)op,       make_float4(a0,a1,a2,a3));
    atomicAdd((float4*)(op + 4), make_float4(a4,a5,a6,a7));
  }
}

// ---------------- K3: out = (out + totV) / (Z' + 1024) -------------------
__global__ void __launch_bounds__(256) k_norm(float* __restrict__ outp){
  int i = blockIdx.x*256 + threadIdx.x;   // 65536 float4 over out region
  int q = i >> 5, c = i & 31;
  float4* o4 = (float4*)outp;
  float4 v = o4[i];
  float4 tv = ((const float4*)g_totV)[((q >> 10) << 5) + c];
  float rz = 1.f/(g_Z[q] + 1024.f);
  v.x = (v.x + tv.x)*rz;
  v.y = (v.y + tv.y)*rz;
  v.z = (v.z + tv.z)*rz;
  v.w = (v.w + tv.w)*rz;
  o4[i] = v;
}

// ---------------- launch ----------------
extern "C" void kernel_launch(void* const* d_in, const int* in_sizes, int n_in,
                              void* d_out, int out_size){
  (void)in_sizes; (void)n_in; (void)out_size;
  const float* x  = (const float*)d_in[0];
  const float* wq = (const float*)d_in[1];
  const float* bq = (const float*)d_in[2];
  const float* wk = (const float*)d_in[3];
  const float* bk = (const float*)d_in[4];
  const float* wv = (const float*)d_in[5];
  const float* bv = (const float*)d_in[6];
  float* out = (float*)d_out;              // (output, attention_truth)

  const int SMM = (128*128 + 128*64 + 64) * 4;   // 98,560 B
  cudaFuncSetAttribute(k_main, cudaFuncAttributeMaxDynamicSharedMemorySize, SMM);

  k_zero <<< ((B_*S_*D_ + B_*S_*S_)/4)/256, 256 >>>(out);
  k_qkv  <<< (B_*S_)/16, 256 >>>(x, wq, bq, wk, bk, wv, bv);
  k_main <<< 144, 512, SMM >>>(out);
  k_norm <<< (B_*S_*D_/4)/256, 256 >>>(out);
}

// round 3
// speedup vs baseline: 1.9038x; 1.1597x over previous
#include <cuda_runtime.h>
#include <cstdint>

#define B_ 2
#define S_ 1024
#define D_ 128

typedef unsigned long long u64;

// ---------------- scratch ----------------
__device__ float g_Qt[B_*D_*S_];     // q' = 1-Q, transposed [b][d][s]
__device__ float g_Kt[B_*D_*S_];     // k' = 1-K, transposed [b][d][s]
__device__ float g_sumK[B_*S_];      // sum_d K (original) per row
__device__ float g_V[B_*S_*D_];      // V [b][s][d]
__device__ float g_Z[B_*S_];         // row sums of E' = exp(10T)-1
__device__ float g_totV[B_*D_];      // sum_s V

__device__ __forceinline__ u64 pack2(float a, float b){
  u64 r; asm("mov.b64 %0, {%1, %2};" : "=l"(r) : "f"(a), "f"(b)); return r;
}
__device__ __forceinline__ void unpack2(u64 v, float& a, float& b){
  asm("mov.b64 {%0, %1}, %2;" : "=f"(a), "=f"(b) : "l"(v));
}
__device__ __forceinline__ u64 fma2(u64 a, u64 b, u64 c){
  u64 d; asm("fma.rn.f32x2 %0, %1, %2, %3;" : "=l"(d) : "l"(a), "l"(b), "l"(c)); return d;
}

// ---------------- K1: QKV (+ zero out/Z) ---------------------------------
// 256 blocks x 256 threads, 8 seq rows per block
__global__ void __launch_bounds__(256) k_qkv(
    const float* __restrict__ x,
    const float* __restrict__ wq, const float* __restrict__ bq,
    const float* __restrict__ wk, const float* __restrict__ bk,
    const float* __restrict__ wv, const float* __restrict__ bv,
    float* __restrict__ outp){
  __shared__ float xs[128][8];   // [d][s]
  __shared__ float wred[8][4];
  int t = threadIdx.x;
  int o = t & 127;               // output dim
  int h = t >> 7;                // row half (4 rows each)
  int s0 = blockIdx.x*8;
  int b  = s0 >> 10;
  int sl = s0 & 1023;

  // zero the out region (exactly 65536 f4 across 256 blocks) + g_Z
  ((float4*)outp)[blockIdx.x*256 + t] = make_float4(0.f,0.f,0.f,0.f);
  if (t < 8) g_Z[blockIdx.x*8 + t] = 0.f;

  // load x tile [8 s][128 d] -> xs[d][s]
  {
    float4 xv = ((const float4*)(x + s0*D_))[t];
    int s_ = t >> 5, d_ = (t & 31)*4;
    xs[d_  ][s_] = xv.x; xs[d_+1][s_] = xv.y;
    xs[d_+2][s_] = xv.z; xs[d_+3][s_] = xv.w;
  }
  __syncthreads();

  u64 aq[2]={0ull,0ull}, ak[2]={0ull,0ull}, av[2]={0ull,0ull};
  #pragma unroll 4
  for (int d=0; d<128; d++){
    float w1 = wq[d*D_+o], w2 = wk[d*D_+o], w3 = wv[d*D_+o];
    u64 w1p = pack2(w1,w1), w2p = pack2(w2,w2), w3p = pack2(w3,w3);
    const u64* xr = (const u64*)&xs[d][h*4];
    u64 x0 = xr[0], x1 = xr[1];
    aq[0]=fma2(x0,w1p,aq[0]); aq[1]=fma2(x1,w1p,aq[1]);
    ak[0]=fma2(x0,w2p,ak[0]); ak[1]=fma2(x1,w2p,ak[1]);
    av[0]=fma2(x0,w3p,av[0]); av[1]=fma2(x1,w3p,av[1]);
  }

  float bqv = bq[o], bkv = bk[o], bvv = bv[o];
  float qv[4], kv[4], vv[4];
  {
    float a0,a1;
    unpack2(aq[0],a0,a1); qv[0]=a0+bqv; qv[1]=a1+bqv;
    unpack2(aq[1],a0,a1); qv[2]=a0+bqv; qv[3]=a1+bqv;
    unpack2(ak[0],a0,a1); kv[0]=a0+bkv; kv[1]=a1+bkv;
    unpack2(ak[1],a0,a1); kv[2]=a0+bkv; kv[3]=a1+bkv;
    unpack2(av[0],a0,a1); vv[0]=a0+bvv; vv[1]=a1+bvv;
    unpack2(av[1],a0,a1); vv[2]=a0+bvv; vv[3]=a1+bvv;
  }
  // primes: q' = 1 - sigmoid(z) = 1/(1+exp(z))
  #pragma unroll
  for (int s=0;s<4;s++){
    qv[s] = 1.f/(1.f+__expf(qv[s]));
    kv[s] = 1.f/(1.f+__expf(kv[s]));
  }

  // V stores (coalesced)
  #pragma unroll
  for (int s=0;s<4;s++) g_V[(s0 + h*4 + s)*D_ + o] = vv[s];

  // transposed Q'/K' stores: one f4 per thread per matrix
  ((float4*)(g_Qt + b*D_*S_ + o*S_ + sl + h*4))[0] =
      make_float4(qv[0],qv[1],qv[2],qv[3]);
  ((float4*)(g_Kt + b*D_*S_ + o*S_ + sl + h*4))[0] =
      make_float4(kv[0],kv[1],kv[2],kv[3]);

  // sumK = 128 - sum_d k'  (warp reduce over o lanes)
  float red[4] = {kv[0],kv[1],kv[2],kv[3]};
  #pragma unroll
  for (int off=16; off>=1; off>>=1){
    #pragma unroll
    for (int s=0;s<4;s++) red[s] += __shfl_xor_sync(0xffffffffu, red[s], off);
  }
  int w = t >> 5;
  if ((t & 31) == 0){
    #pragma unroll
    for (int s=0;s<4;s++) wred[w][s] = red[s];
  }
  __syncthreads();
  if (t < 8){
    int s = t, hh = s >> 2, p = s & 3;
    float tot = wred[hh*4+0][p]+wred[hh*4+1][p]+wred[hh*4+2][p]+wred[hh*4+3][p];
    g_sumK[s0 + s] = 128.f - tot;
  }
}

// ---------------- K2: fused truth + E' + Z + E'@V + att-zero + totV ------
// 256 blocks: 0..143 compute (lower-triangle tiles), 144..255 zero upper tiles
__global__ void __launch_bounds__(512) k_main(float* __restrict__ outp){
  extern __shared__ float sm[];
  float* Qts = sm;               // [128 d][128 q]  -> reused as Vs
  float* Kts = sm + 128*128;     // [128 d][64 k]   -> reused as Es
  float* sKs = Kts + 128*64;     // [64]
  int bid = blockIdx.x;
  int t = threadIdx.x;
  float* att = outp + B_*S_*D_;

  if (bid >= 144){
    // ---- zero an upper-triangle att tile (128q x 64k) ----
    int u = bid - 144, b = u/56, uu = u - b*56;
    int qt = 0, cum = 0;
    while (cum + (14 - 2*qt) <= uu){ cum += 14 - 2*qt; qt++; }
    int kt = 2*qt + 2 + (uu - cum);
    int q0 = qt*128, k0 = kt*64;
    float4 z4 = make_float4(0.f,0.f,0.f,0.f);
    #pragma unroll
    for (int it=0; it<4; it++){
      int i = t + it*512;
      int row = i >> 4, col = i & 15;
      ((float4*)(att + (b*S_ + q0 + row)*S_ + k0))[col] = z4;
    }
    // ---- one block per batch also reduces totV ----
    if (uu == 0){
      int d = t & 127, g = t >> 7;   // 4 groups x 256 rows
      const float* Vb = g_V + b*S_*D_;
      float a = 0.f;
      for (int s = g*256; s < (g+1)*256; s++) a += Vb[s*D_ + d];
      float* redv = sm;              // reuse dynamic smem
      redv[g*128 + d] = a;
      __syncthreads();
      if (t < 128)
        g_totV[b*D_ + t] = redv[t] + redv[128+t] + redv[256+t] + redv[384+t];
    }
    return;
  }

  // ---- compute tile ----
  int b = bid/72, r = bid - b*72;
  int qt = 0;
  while ((qt+1)*(qt+2) <= r) qt++;
  int k0 = (r - qt*(qt+1))*64;
  int q0 = qt*128;
  int tx = t & 15, ty = t >> 4;    // ty 0..31

  const float4* Qg = (const float4*)(g_Qt + b*D_*S_);
  const float4* Kg = (const float4*)(g_Kt + b*D_*S_);
  const float4* Vg = (const float4*)(g_V + b*S_*D_);

  // prefetch V tile into registers (consumed in phase 3)
  float4 vpre[4];
  #pragma unroll
  for (int it=0; it<4; it++){
    int i = t + it*512;
    vpre[it] = Vg[(k0 + (i>>5))*32 + (i&31)];
  }

  float4* Qts4 = (float4*)Qts;
  float4* Kts4 = (float4*)Kts;
  #pragma unroll
  for (int it=0; it<8; it++){
    int i = t + it*512;                     // 4096 f4
    Qts4[i] = Qg[(i>>5)*256 + (q0>>2) + (i&31)];
  }
  #pragma unroll
  for (int it=0; it<4; it++){
    int i = t + it*512;                     // 2048 f4
    Kts4[i] = Kg[(i>>4)*256 + (k0>>2) + (i&15)];
  }
  if (t < 64) sKs[t] = g_sumK[b*S_ + k0 + t];
  __syncthreads();

  // phase 1: acc = sum_d [k' <= q'] * k'    (FSET + FFMA, no predicates)
  float acc[4][4];
  #pragma unroll
  for (int i=0;i<4;i++)
    #pragma unroll
    for (int j=0;j<4;j++) acc[i][j] = 0.f;

  #pragma unroll 4
  for (int d=0; d<128; d++){
    float4 qa = Qts4[d*32 + ty];
    float4 kf = Kts4[d*16 + tx];
    float qq[4] = {qa.x,qa.y,qa.z,qa.w};
    float kk[4] = {kf.x,kf.y,kf.z,kf.w};
    #pragma unroll
    for (int i=0;i<4;i++){
      #pragma unroll
      for (int j=0;j<4;j++){
        asm("{.reg .f32 m; set.le.f32.f32 m, %1, %2; fma.rn.f32 %0, m, %1, %0;}"
            : "+f"(acc[i][j]) : "f"(kk[j]), "f"(qq[i]));
      }
    }
  }

  // phase 2: T, att store, E' = exp(10T)-1, Z partial
  const float inv = 1.f/128.f;
  float e[4][4];
  #pragma unroll
  for (int i=0;i<4;i++){
    int qg = q0 + ty*4 + i;
    float zrow = 0.f;
    float tt[4];
    #pragma unroll
    for (int j=0;j<4;j++){
      int kg = k0 + tx*4 + j;
      float T = (acc[i][j] + sKs[tx*4+j]) * inv;
      bool val = (kg <= qg);
      T = val ? T : 0.f;
      float ee = val ? (__expf(10.f*T) - 1.f) : 0.f;
      tt[j] = T; e[i][j] = ee; zrow += ee;
    }
    ((float4*)(att + (b*S_ + qg)*S_ + k0 + tx*4))[0] =
        make_float4(tt[0],tt[1],tt[2],tt[3]);
    #pragma unroll
    for (int off=8; off>=1; off>>=1)
      zrow += __shfl_xor_sync(0xffffffffu, zrow, off);
    if (tx == 0) atomicAdd(&g_Z[b*S_ + qg], zrow);
  }
  __syncthreads();    // all reads of Qts/Kts done

  // phase 3: stage E' (Kts region) + V (Qts region, from registers)
  float* Es = Kts;               // [64 k][128 q]
  float* Vs = Qts;               // [64 k][128 d]
  #pragma unroll
  for (int j=0;j<4;j++){
    int kl = tx*4 + j;
    ((float4*)(Es + kl*128 + ty*4))[0] =
        make_float4(e[0][j], e[1][j], e[2][j], e[3][j]);
  }
  float4* Vs4 = (float4*)Vs;
  #pragma unroll
  for (int it=0; it<4; it++){
    int i = t + it*512;
    Vs4[i] = vpre[it];
  }
  __syncthreads();

  // phase 4: out[q0:q0+128][:] += E'^T @ V   (4q x 8d per thread, f32x2)
  u64 acc2[4][4];
  #pragma unroll
  for (int i=0;i<4;i++)
    #pragma unroll
    for (int j=0;j<4;j++) acc2[i][j] = 0ull;

  float4* Es4 = (float4*)Es;
  #pragma unroll 2
  for (int k=0;k<64;k++){
    float4 ef = Es4[k*32 + ty];
    const u64* vr = (const u64*)(Vs + k*128 + tx*8);
    u64 v0 = vr[0], v1 = vr[1], v2 = vr[2], v3 = vr[3];
    float ev[4] = {ef.x,ef.y,ef.z,ef.w};
    #pragma unroll
    for (int i=0;i<4;i++){
      u64 e2 = pack2(ev[i], ev[i]);
      acc2[i][0] = fma2(e2, v0, acc2[i][0]);
      acc2[i][1] = fma2(e2, v1, acc2[i][1]);
      acc2[i][2] = fma2(e2, v2, acc2[i][2]);
      acc2[i][3] = fma2(e2, v3, acc2[i][3]);
    }
  }

  #pragma unroll
  for (int i=0;i<4;i++){
    int qg = q0 + ty*4 + i;
    float* op = outp + (b*S_ + qg)*D_ + tx*8;
    float a0,a1,a2,a3,a4,a5,a6,a7;
    unpack2(acc2[i][0],a0,a1);
    unpack2(acc2[i][1],a2,a3);
    unpack2(acc2[i][2],a4,a5);
    unpack2(acc2[i][3],a6,a7);
    atomicAdd((float4*)op,       make_float4(a0,a1,a2,a3));
    atomicAdd((float4*)(op + 4), make_float4(a4,a5,a6,a7));
  }
}

// ---------------- K3: out = (out + totV) / (Z + 1024) --------------------
__global__ void __launch_bounds__(256) k_norm(float* __restrict__ outp){
  int i1 = blockIdx.x*256 + threadIdx.x;   // grid 128 -> 32768 threads
  int i2 = i1 + 32768;
  float4* o4 = (float4*)outp;
  float4 v1 = o4[i1];
  float4 v2 = o4[i2];
  int q1 = i1 >> 5, q2 = i2 >> 5;
  float4 tv1 = ((const float4*)g_totV)[((q1 >> 10) << 5) + (i1 & 31)];
  float4 tv2 = ((const float4*)g_totV)[((q2 >> 10) << 5) + (i2 & 31)];
  float z1 = g_Z[q1], z2 = g_Z[q2];
  float rz1 = 1.f/(z1 + 1024.f), rz2 = 1.f/(z2 + 1024.f);
  v1.x=(v1.x+tv1.x)*rz1; v1.y=(v1.y+tv1.y)*rz1;
  v1.z=(v1.z+tv1.z)*rz1; v1.w=(v1.w+tv1.w)*rz1;
  v2.x=(v2.x+tv2.x)*rz2; v2.y=(v2.y+tv2.y)*rz2;
  v2.z=(v2.z+tv2.z)*rz2; v2.w=(v2.w+tv2.w)*rz2;
  o4[i1] = v1;
  o4[i2] = v2;
}

// ---------------- launch ----------------
extern "C" void kernel_launch(void* const* d_in, const int* in_sizes, int n_in,
                              void* d_out, int out_size){
  (void)in_sizes; (void)n_in; (void)out_size;
  const float* x  = (const float*)d_in[0];
  const float* wq = (const float*)d_in[1];
  const float* bq = (const float*)d_in[2];
  const float* wk = (const float*)d_in[3];
  const float* bk = (const float*)d_in[4];
  const float* wv = (const float*)d_in[5];
  const float* bv = (const float*)d_in[6];
  float* out = (float*)d_out;              // (output, attention_truth)

  const int SMM = (128*128 + 128*64 + 64) * 4;   // 98,560 B
  cudaFuncSetAttribute(k_main, cudaFuncAttributeMaxDynamicSharedMemorySize, SMM);

  k_qkv  <<< 256, 256 >>>(x, wq, bq, wk, bk, wv, bv, out);
  k_main <<< 256, 512, SMM >>>(out);
  k_norm <<< 128, 256 >>>(out);
}

// round 4
// speedup vs baseline: 2.0149x; 1.0584x over previous
#include <cuda_runtime.h>
#include <cstdint>

#define B_ 2
#define S_ 1024
#define D_ 128

typedef unsigned long long u64;

// ---------------- scratch ----------------
__device__ float g_Qt[B_*D_*S_];     // q' = 1-Q, transposed [b][d][s]
__device__ float g_Kt[B_*D_*S_];     // k' = 1-K, transposed [b][d][s]
__device__ float g_sumK[B_*S_];      // sum_d K (original) per row
__device__ float g_V[B_*S_*D_];      // V [b][s][d]
__device__ float g_Z[B_*S_];         // row sums of E' = exp(10T)-1
__device__ float g_totV[B_*D_];      // sum_s V

__device__ __forceinline__ u64 pack2(float a, float b){
  u64 r; asm("mov.b64 %0, {%1, %2};" : "=l"(r) : "f"(a), "f"(b)); return r;
}
__device__ __forceinline__ void unpack2(u64 v, float& a, float& b){
  asm("mov.b64 {%0, %1}, %2;" : "=f"(a), "=f"(b) : "l"(v));
}
__device__ __forceinline__ u64 fma2(u64 a, u64 b, u64 c){
  u64 d; asm("fma.rn.f32x2 %0, %1, %2, %3;" : "=l"(d) : "l"(a), "l"(b), "l"(c)); return d;
}

// ---------------- K1: QKV (+ zero out/Z) ---------------------------------
// 128 blocks x 512 threads, 16 seq rows per block.
// Weights staged in smem, 4 chunks of 32 d-rows, double-buffered.
// fma2 packs (even d, odd d) partial sums.
__global__ void __launch_bounds__(512) k_qkv(
    const float* __restrict__ x,
    const float* __restrict__ wq, const float* __restrict__ bq,
    const float* __restrict__ wk, const float* __restrict__ bk,
    const float* __restrict__ wv, const float* __restrict__ bv,
    float* __restrict__ outp){
  extern __shared__ float sm[];
  float* ws = sm;                 // [2][3][32][128]  = 24576 floats
  float* xs = sm + 24576;         // [16][128]        = 2048 floats
  __shared__ float wred[16][4];

  int t = threadIdx.x;
  int o = t & 127;                // output dim
  int h = t >> 7;                 // row group (4 rows each), 0..3
  int s0 = blockIdx.x*16;
  int b  = s0 >> 10;
  int sl = s0 & 1023;

  // zero the out region (65536 f4 over 128 blocks) + g_Z
  ((float4*)outp)[blockIdx.x*512 + t] = make_float4(0.f,0.f,0.f,0.f);
  if (t < 16) g_Z[blockIdx.x*16 + t] = 0.f;

  // stage x tile [16 s][128 d] row-major (1 f4/thread, conflict-free)
  ((float4*)xs)[t] = ((const float4*)(x + s0*D_))[t];

  const float4* wq4 = (const float4*)wq;
  const float4* wk4 = (const float4*)wk;
  const float4* wv4 = (const float4*)wv;
  float4* ws4 = (float4*)ws;

  // stage chunk 0 into buffer 0
  #pragma unroll
  for (int j=0;j<6;j++){
    int i = t + j*512;            // 0..3071 f4 of a chunk
    int m = i >> 10, r = i & 1023;
    const float4* src = (m==0)? wq4 : (m==1)? wk4 : wv4;
    ws4[i] = src[((r>>5))*32 + (r&31)];
  }
  __syncthreads();

  u64 aq[4], ak[4], av[4];
  #pragma unroll
  for (int jr=0;jr<4;jr++){ aq[jr]=0ull; ak[jr]=0ull; av[jr]=0ull; }

  #pragma unroll 1
  for (int c=0; c<4; c++){
    // prefetch chunk c+1 into other buffer (no sync yet)
    if (c < 3){
      int f = (c+1)&1;
      #pragma unroll
      for (int j=0;j<6;j++){
        int i = t + j*512;
        int m = i >> 10, r = i & 1023;
        const float4* src = (m==0)? wq4 : (m==1)? wk4 : wv4;
        ws4[f*3072 + i] = src[((c+1)*32 + (r>>5))*32 + (r&31)];
      }
    }
    const float* wb = ws + (c&1)*12288;
    #pragma unroll 4
    for (int dp=0; dp<16; dp++){
      int d0 = dp*2;
      u64 xp0 = *(const u64*)&xs[(h*4+0)*128 + c*32 + d0];
      u64 xp1 = *(const u64*)&xs[(h*4+1)*128 + c*32 + d0];
      u64 xp2 = *(const u64*)&xs[(h*4+2)*128 + c*32 + d0];
      u64 xp3 = *(const u64*)&xs[(h*4+3)*128 + c*32 + d0];
      u64 wqp = pack2(wb[          d0*128 + o], wb[          (d0+1)*128 + o]);
      u64 wkp = pack2(wb[ 4096 +   d0*128 + o], wb[ 4096 +   (d0+1)*128 + o]);
      u64 wvp = pack2(wb[ 8192 +   d0*128 + o], wb[ 8192 +   (d0+1)*128 + o]);
      aq[0]=fma2(wqp,xp0,aq[0]); aq[1]=fma2(wqp,xp1,aq[1]);
      aq[2]=fma2(wqp,xp2,aq[2]); aq[3]=fma2(wqp,xp3,aq[3]);
      ak[0]=fma2(wkp,xp0,ak[0]); ak[1]=fma2(wkp,xp1,ak[1]);
      ak[2]=fma2(wkp,xp2,ak[2]); ak[3]=fma2(wkp,xp3,ak[3]);
      av[0]=fma2(wvp,xp0,av[0]); av[1]=fma2(wvp,xp1,av[1]);
      av[2]=fma2(wvp,xp2,av[2]); av[3]=fma2(wvp,xp3,av[3]);
    }
    __syncthreads();
  }

  float bqv = bq[o], bkv = bk[o], bvv = bv[o];
  float qv[4], kv[4], vv[4];
  #pragma unroll
  for (int jr=0;jr<4;jr++){
    float a0,a1;
    unpack2(aq[jr],a0,a1); qv[jr] = a0+a1+bqv;
    unpack2(ak[jr],a0,a1); kv[jr] = a0+a1+bkv;
    unpack2(av[jr],a0,a1); vv[jr] = a0+a1+bvv;
  }
  // primes: q' = 1 - sigmoid(z) = 1/(1+exp(z))
  #pragma unroll
  for (int jr=0;jr<4;jr++){
    qv[jr] = 1.f/(1.f+__expf(qv[jr]));
    kv[jr] = 1.f/(1.f+__expf(kv[jr]));
  }

  // V stores (coalesced)
  #pragma unroll
  for (int jr=0;jr<4;jr++) g_V[(s0 + h*4 + jr)*D_ + o] = vv[jr];

  // transposed Q'/K' stores: one f4 per thread per matrix
  ((float4*)(g_Qt + b*D_*S_ + o*S_ + sl + h*4))[0] =
      make_float4(qv[0],qv[1],qv[2],qv[3]);
  ((float4*)(g_Kt + b*D_*S_ + o*S_ + sl + h*4))[0] =
      make_float4(kv[0],kv[1],kv[2],kv[3]);

  // sumK = 128 - sum_d k'  (reduce over o: warp shuffle + cross-warp)
  float red[4] = {kv[0],kv[1],kv[2],kv[3]};
  #pragma unroll
  for (int off=16; off>=1; off>>=1){
    #pragma unroll
    for (int jr=0;jr<4;jr++) red[jr] += __shfl_xor_sync(0xffffffffu, red[jr], off);
  }
  int w = t >> 5;
  if ((t & 31) == 0){
    #pragma unroll
    for (int jr=0;jr<4;jr++) wred[w][jr] = red[jr];
  }
  __syncthreads();
  if (t < 16){
    int r = t, hh = r >> 2, jr = r & 3;
    float tot = wred[hh*4+0][jr]+wred[hh*4+1][jr]+wred[hh*4+2][jr]+wred[hh*4+3][jr];
    g_sumK[s0 + r] = 128.f - tot;
  }
}

// ---------------- K2: fused truth + E' + Z + E'@V + att-zero + totV ------
// 256 blocks: 0..143 compute (lower-triangle tiles), 144..255 zero upper tiles
__global__ void __launch_bounds__(512) k_main(float* __restrict__ outp){
  extern __shared__ float sm[];
  float* Qts = sm;               // [128 d][128 q]  -> reused as Vs
  float* Kts = sm + 128*128;     // [128 d][64 k]   -> reused as Es
  float* sKs = Kts + 128*64;     // [64]
  int bid = blockIdx.x;
  int t = threadIdx.x;
  float* att = outp + B_*S_*D_;

  if (bid >= 144){
    // ---- zero an upper-triangle att tile (128q x 64k) ----
    int u = bid - 144, b = u/56, uu = u - b*56;
    int qt = 0, cum = 0;
    while (cum + (14 - 2*qt) <= uu){ cum += 14 - 2*qt; qt++; }
    int kt = 2*qt + 2 + (uu - cum);
    int q0 = qt*128, k0 = kt*64;
    float4 z4 = make_float4(0.f,0.f,0.f,0.f);
    #pragma unroll
    for (int it=0; it<4; it++){
      int i = t + it*512;
      int row = i >> 4, col = i & 15;
      ((float4*)(att + (b*S_ + q0 + row)*S_ + k0))[col] = z4;
    }
    // ---- one block per batch also reduces totV ----
    if (uu == 0){
      int d = t & 127, g = t >> 7;   // 4 groups x 256 rows
      const float* Vb = g_V + b*S_*D_;
      float a = 0.f;
      for (int s = g*256; s < (g+1)*256; s++) a += Vb[s*D_ + d];
      float* redv = sm;              // reuse dynamic smem
      redv[g*128 + d] = a;
      __syncthreads();
      if (t < 128)
        g_totV[b*D_ + t] = redv[t] + redv[128+t] + redv[256+t] + redv[384+t];
    }
    return;
  }

  // ---- compute tile ----
  int b = bid/72, r = bid - b*72;
  int qt = 0;
  while ((qt+1)*(qt+2) <= r) qt++;
  int k0 = (r - qt*(qt+1))*64;
  int q0 = qt*128;
  int tx = t & 15, ty = t >> 4;    // ty 0..31

  const float4* Qg = (const float4*)(g_Qt + b*D_*S_);
  const float4* Kg = (const float4*)(g_Kt + b*D_*S_);
  const float4* Vg = (const float4*)(g_V + b*S_*D_);

  // prefetch V tile into registers (consumed in phase 3)
  float4 vpre[4];
  #pragma unroll
  for (int it=0; it<4; it++){
    int i = t + it*512;
    vpre[it] = Vg[(k0 + (i>>5))*32 + (i&31)];
  }

  float4* Qts4 = (float4*)Qts;
  float4* Kts4 = (float4*)Kts;
  #pragma unroll
  for (int it=0; it<8; it++){
    int i = t + it*512;                     // 4096 f4
    Qts4[i] = Qg[(i>>5)*256 + (q0>>2) + (i&31)];
  }
  #pragma unroll
  for (int it=0; it<4; it++){
    int i = t + it*512;                     // 2048 f4
    Kts4[i] = Kg[(i>>4)*256 + (k0>>2) + (i&15)];
  }
  if (t < 64) sKs[t] = g_sumK[b*S_ + k0 + t];
  __syncthreads();

  // phase 1: acc = sum_d [k' <= q'] * k'    (FSET + FFMA, no predicates)
  float acc[4][4];
  #pragma unroll
  for (int i=0;i<4;i++)
    #pragma unroll
    for (int j=0;j<4;j++) acc[i][j] = 0.f;

  #pragma unroll 4
  for (int d=0; d<128; d++){
    float4 qa = Qts4[d*32 + ty];
    float4 kf = Kts4[d*16 + tx];
    float qq[4] = {qa.x,qa.y,qa.z,qa.w};
    float kk[4] = {kf.x,kf.y,kf.z,kf.w};
    #pragma unroll
    for (int i=0;i<4;i++){
      #pragma unroll
      for (int j=0;j<4;j++){
        asm("{.reg .f32 m; set.le.f32.f32 m, %1, %2; fma.rn.f32 %0, m, %1, %0;}"
            : "+f"(acc[i][j]) : "f"(kk[j]), "f"(qq[i]));
      }
    }
  }

  // phase 2: T, att store, E' = exp(10T)-1, Z partial
  const float inv = 1.f/128.f;
  float e[4][4];
  #pragma unroll
  for (int i=0;i<4;i++){
    int qg = q0 + ty*4 + i;
    float zrow = 0.f;
    float tt[4];
    #pragma unroll
    for (int j=0;j<4;j++){
      int kg = k0 + tx*4 + j;
      float T = (acc[i][j] + sKs[tx*4+j]) * inv;
      bool val = (kg <= qg);
      T = val ? T : 0.f;
      float ee = val ? (__expf(10.f*T) - 1.f) : 0.f;
      tt[j] = T; e[i][j] = ee; zrow += ee;
    }
    ((float4*)(att + (b*S_ + qg)*S_ + k0 + tx*4))[0] =
        make_float4(tt[0],tt[1],tt[2],tt[3]);
    #pragma unroll
    for (int off=8; off>=1; off>>=1)
      zrow += __shfl_xor_sync(0xffffffffu, zrow, off);
    if (tx == 0) atomicAdd(&g_Z[b*S_ + qg], zrow);
  }
  __syncthreads();    // all reads of Qts/Kts done

  // phase 3: stage E' (Kts region) + V (Qts region, from registers)
  float* Es = Kts;               // [64 k][128 q]
  float* Vs = Qts;               // [64 k][128 d]
  #pragma unroll
  for (int j=0;j<4;j++){
    int kl = tx*4 + j;
    ((float4*)(Es + kl*128 + ty*4))[0] =
        make_float4(e[0][j], e[1][j], e[2][j], e[3][j]);
  }
  float4* Vs4 = (float4*)Vs;
  #pragma unroll
  for (int it=0; it<4; it++){
    int i = t + it*512;
    Vs4[i] = vpre[it];
  }
  __syncthreads();

  // phase 4: out[q0:q0+128][:] += E'^T @ V   (4q x 8d per thread, f32x2)
  u64 acc2[4][4];
  #pragma unroll
  for (int i=0;i<4;i++)
    #pragma unroll
    for (int j=0;j<4;j++) acc2[i][j] = 0ull;

  float4* Es4 = (float4*)Es;
  #pragma unroll 2
  for (int k=0;k<64;k++){
    float4 ef = Es4[k*32 + ty];
    const u64* vr = (const u64*)(Vs + k*128 + tx*8);
    u64 v0 = vr[0], v1 = vr[1], v2 = vr[2], v3 = vr[3];
    float ev[4] = {ef.x,ef.y,ef.z,ef.w};
    #pragma unroll
    for (int i=0;i<4;i++){
      u64 e2 = pack2(ev[i], ev[i]);
      acc2[i][0] = fma2(e2, v0, acc2[i][0]);
      acc2[i][1] = fma2(e2, v1, acc2[i][1]);
      acc2[i][2] = fma2(e2, v2, acc2[i][2]);
      acc2[i][3] = fma2(e2, v3, acc2[i][3]);
    }
  }

  #pragma unroll
  for (int i=0;i<4;i++){
    int qg = q0 + ty*4 + i;
    float* op = outp + (b*S_ + qg)*D_ + tx*8;
    float a0,a1,a2,a3,a4,a5,a6,a7;
    unpack2(acc2[i][0],a0,a1);
    unpack2(acc2[i][1],a2,a3);
    unpack2(acc2[i][2],a4,a5);
    unpack2(acc2[i][3],a6,a7);
    atomicAdd((float4*)op,       make_float4(a0,a1,a2,a3));
    atomicAdd((float4*)(op + 4), make_float4(a4,a5,a6,a7));
  }
}

// ---------------- K3: out = (out + totV) / (Z + 1024) --------------------
__global__ void __launch_bounds__(256) k_norm(float* __restrict__ outp){
  int i1 = blockIdx.x*256 + threadIdx.x;   // grid 128 -> 32768 threads
  int i2 = i1 + 32768;
  float4* o4 = (float4*)outp;
  float4 v1 = o4[i1];
  float4 v2 = o4[i2];
  int q1 = i1 >> 5, q2 = i2 >> 5;
  float4 tv1 = ((const float4*)g_totV)[((q1 >> 10) << 5) + (i1 & 31)];
  float4 tv2 = ((const float4*)g_totV)[((q2 >> 10) << 5) + (i2 & 31)];
  float z1 = g_Z[q1], z2 = g_Z[q2];
  float rz1 = 1.f/(z1 + 1024.f), rz2 = 1.f/(z2 + 1024.f);
  v1.x=(v1.x+tv1.x)*rz1; v1.y=(v1.y+tv1.y)*rz1;
  v1.z=(v1.z+tv1.z)*rz1; v1.w=(v1.w+tv1.w)*rz1;
  v2.x=(v2.x+tv2.x)*rz2; v2.y=(v2.y+tv2.y)*rz2;
  v2.z=(v2.z+tv2.z)*rz2; v2.w=(v2.w+tv2.w)*rz2;
  o4[i1] = v1;
  o4[i2] = v2;
}

// ---------------- launch ----------------
extern "C" void kernel_launch(void* const* d_in, const int* in_sizes, int n_in,
                              void* d_out, int out_size){
  (void)in_sizes; (void)n_in; (void)out_size;
  const float* x  = (const float*)d_in[0];
  const float* wq = (const float*)d_in[1];
  const float* bq = (const float*)d_in[2];
  const float* wk = (const float*)d_in[3];
  const float* bk = (const float*)d_in[4];
  const float* wv = (const float*)d_in[5];
  const float* bv = (const float*)d_in[6];
  float* out = (float*)d_out;              // (output, attention_truth)

  const int SMQ = (24576 + 2048) * 4;            // 106,496 B
  const int SMM = (128*128 + 128*64 + 64) * 4;   // 98,560 B
  cudaFuncSetAttribute(k_qkv,  cudaFuncAttributeMaxDynamicSharedMemorySize, SMQ);
  cudaFuncSetAttribute(k_main, cudaFuncAttributeMaxDynamicSharedMemorySize, SMM);

  k_qkv  <<< 128, 512, SMQ >>>(x, wq, bq, wk, bk, wv, bv, out);
  k_main <<< 256, 512, SMM >>>(out);
  k_norm <<< 128, 256 >>>(out);
}